// round 1
// baseline (speedup 1.0000x reference)
#include <cuda_runtime.h>
#include <math.h>

// ---------------- problem constants ----------------
#define BS   16
#define TT   50
#define NA   3
#define NC   80
#define HH   76
#define WW   76
#define NCH  255
#define HW   (HH*WW)               // 5776
#define CELLS_PER_B (NA*HW)        // 17328
#define TPB  256
#define BLKS_PER_B ((CELLS_PER_B + TPB - 1)/TPB)  // 68

// ---------------- device scratch (no allocations allowed) ----------------
__device__ float  g_tbox[BS*TT*4];   // gx, gy, gw, gh per target
__device__ int    g_tinfo[BS*TT*4];  // ai(-1 if no write), gi, gj, cls
__device__ float  g_tvals[BS*TT*5];  // tx, ty, tw, th, scale
__device__ int    g_tvalid[BS*TT];
__device__ double g_acc[8];          // lx, ly, lw, lh, lobj, lnoobj, lcls, n_obj

// scaled anchors (TOTAL / STRIDE=8)
__constant__ float c_staw[9] = {1.25f, 2.0f, 4.125f, 3.75f, 7.75f, 7.375f, 14.5f, 19.5f, 46.625f};
__constant__ float c_stah[9] = {1.625f, 3.75f, 2.875f, 7.625f, 5.625f, 14.875f, 11.25f, 24.75f, 40.75f};
__constant__ float c_saw[3]  = {1.25f, 2.0f, 4.125f};
__constant__ float c_sah[3]  = {1.625f, 3.75f, 2.875f};

// ---------------- reference-exact helpers ----------------
__device__ __forceinline__ float f_iou(float b1x, float b1y, float b1w, float b1h,
                                       float b2x, float b2y, float b2w, float b2h) {
    float b1x1 = b1x - b1w * 0.5f, b1x2 = b1x + b1w * 0.5f;
    float b1y1 = b1y - b1h * 0.5f, b1y2 = b1y + b1h * 0.5f;
    float b2x1 = b2x - b2w * 0.5f, b2x2 = b2x + b2w * 0.5f;
    float b2y1 = b2y - b2h * 0.5f, b2y2 = b2y + b2h * 0.5f;
    float iw = fminf(b1x2, b2x2) - fmaxf(b1x1, b2x1); iw = fmaxf(iw, 0.f);
    float ih = fminf(b1y2, b2y2) - fmaxf(b1y1, b2y1); ih = fmaxf(ih, 0.f);
    float inter = iw * ih;
    float a1 = (b1x2 - b1x1) * (b1y2 - b1y1);
    float a2 = (b2x2 - b2x1) * (b2y2 - b2y1);
    return inter / (a1 + a2 - inter + 1e-16f);
}

__device__ __forceinline__ float safelog(float p) { return p > 0.f ? logf(p) : -100.0f; }
__device__ __forceinline__ float bce(float p, float t) {
    return -(t * safelog(p) + (1.f - t) * safelog(1.f - p));
}
__device__ __forceinline__ float sl1(float p, float t) {
    float d = fabsf(p - t);
    return d < 1.f ? 0.5f * d * d : d - 0.5f;
}
__device__ __forceinline__ float sigm(float z) { return 1.f / (1.f + expf(-z)); }

// ---------------- kernel 1: target preprocess (+ accumulator reset) ----------------
__global__ void prep_kernel(const float* __restrict__ tgt) {
    int tid = threadIdx.x;
    if (tid < 8) g_acc[tid] = 0.0;
    __syncthreads();
    if (tid >= BS * TT) return;

    const float* p = tgt + (size_t)tid * 5;
    float t0 = p[0], t1 = p[1], t2 = p[2], t3 = p[3], t4 = p[4];
    int valid = ((t0 + t1 + t2 + t3 + t4) != 0.f) ? 1 : 0;

    float gx = t1 * (float)WW, gy = t2 * (float)HH;
    float gw = t3 * (float)WW, gh = t4 * (float)HH;
    int gi = (int)gx, gj = (int)gy;

    // anchor matching against 9 scaled total anchors; first-max argmax
    float best = -1e30f; int bestn = 0;
#pragma unroll
    for (int n = 0; n < 9; n++) {
        float v = f_iou(0.f, 0.f, gw, gh, 0.f, 0.f, c_staw[n], c_stah[n]);
        if (v > best) { best = v; bestn = n; }
    }
    int ai = (bestn < 3) ? bestn : -1;   // LUT: [0,1,2,-1,...]
    int wr = (valid && ai >= 0) ? ai : -1;

    g_tbox[tid*4+0] = gx; g_tbox[tid*4+1] = gy;
    g_tbox[tid*4+2] = gw; g_tbox[tid*4+3] = gh;
    g_tvalid[tid] = valid;
    g_tinfo[tid*4+0] = wr;
    g_tinfo[tid*4+1] = gi;
    g_tinfo[tid*4+2] = gj;
    g_tinfo[tid*4+3] = (int)t0;

    float tx = 0.f, ty = 0.f, twv = 0.f, thv = 0.f, sc = 0.f;
    if (wr >= 0) {
        tx  = gx - (float)gi;
        ty  = gy - (float)gj;
        twv = logf(gw / c_saw[wr] + 1e-16f);
        thv = logf(gh / c_sah[wr] + 1e-16f);
        sc  = 2.0f - t3 * t4;
    }
    g_tvals[tid*5+0] = tx;  g_tvals[tid*5+1] = ty;
    g_tvals[tid*5+2] = twv; g_tvals[tid*5+3] = thv;
    g_tvals[tid*5+4] = sc;

    if (valid) atomicAdd(&g_acc[7], 1.0);
}

// ---------------- kernel 2: per-cell loss ----------------
__global__ void __launch_bounds__(TPB) main_kernel(const float* __restrict__ inp) {
    __shared__ float sbox[TT][4];
    __shared__ float svals[TT][5];
    __shared__ int   sai[TT], sgi[TT], sgj[TT], scls[TT], sval[TT];

    int b = blockIdx.x / BLKS_PER_B;
    int local = (blockIdx.x % BLKS_PER_B) * TPB + threadIdx.x;

    for (int t = threadIdx.x; t < TT; t += TPB) {
        int g = b * TT + t;
        sbox[t][0] = g_tbox[g*4+0]; sbox[t][1] = g_tbox[g*4+1];
        sbox[t][2] = g_tbox[g*4+2]; sbox[t][3] = g_tbox[g*4+3];
        sval[t] = g_tvalid[g];
        sai[t]  = g_tinfo[g*4+0];
        sgi[t]  = g_tinfo[g*4+1];
        sgj[t]  = g_tinfo[g*4+2];
        scls[t] = g_tinfo[g*4+3];
        svals[t][0] = g_tvals[g*5+0]; svals[t][1] = g_tvals[g*5+1];
        svals[t][2] = g_tvals[g*5+2]; svals[t][3] = g_tvals[g*5+3];
        svals[t][4] = g_tvals[g*5+4];
    }
    __syncthreads();

    float lx = 0.f, ly = 0.f, lw_ = 0.f, lh_ = 0.f;
    float lobj = 0.f, lnoobj = 0.f, lcls = 0.f;

    if (local < CELLS_PER_B) {
        int a = local / HW;
        int r = local - a * HW;
        int j = r / WW;
        int i = r - j * WW;

        const float* base = inp + (size_t)(b * NCH + a * 85) * HW + r;
        float sx = sigm(base[0]);
        float sy = sigm(base[HW]);
        float wv = base[2*HW];
        float hv = base[3*HW];
        float cf = sigm(base[4*HW]);

        float px = sx + (float)i;
        float py = sy + (float)j;
        float pw = expf(wv) * c_saw[a];
        float ph = expf(hv) * c_sah[a];

        bool ign = false;
        int last = -1;
        unsigned cb0 = 0, cb1 = 0, cb2 = 0;

        for (int t = 0; t < TT; t++) {
            if (!sval[t]) continue;   // uniform across block (shared), no divergence
            float v = f_iou(sbox[t][0], sbox[t][1], sbox[t][2], sbox[t][3],
                            px, py, pw, ph);
            ign = ign || (v >= 0.5f);
            // scatter resolution fused into the IoU scan; last writer wins (ascending t)
            if (sai[t] == a && sgj[t] == j && sgi[t] == i) {
                last = t;
                int c = scls[t];
                if (c < 32)      cb0 |= 1u << c;
                else if (c < 64) cb1 |= 1u << (c - 32);
                else             cb2 |= 1u << (c - 64);
            }
        }

        if (last >= 0) {
            float tx = svals[last][0], ty = svals[last][1];
            float tw = svals[last][2], th = svals[last][3];
            float sc = svals[last][4];
            lx   = sc * bce(sx, tx);
            ly   = sc * bce(sy, ty);
            lw_  = sc * sl1(wv, tw);
            lh_  = sc * sl1(hv, th);
            lobj = -safelog(cf);       // bce(conf, 1)
            for (int c = 0; c < NC; c++) {
                float pc = sigm(base[(5 + c) * HW]);
                unsigned bit = ((c < 32) ? (cb0 >> c)
                              : (c < 64) ? (cb1 >> (c - 32))
                                         : (cb2 >> (c - 64))) & 1u;
                lcls += bit ? -safelog(pc) : -safelog(1.f - pc);
            }
        } else if (!ign) {
            lnoobj = -safelog(1.f - cf);  // bce(conf, 0)
        }
        // non-mask, ignored cells contribute 0 everywhere (noobj=0, scales=0, bce(0,0)=0)
    }

    // warp reduce 7 scalars, then per-warp double atomics
    unsigned m = 0xffffffffu;
#pragma unroll
    for (int off = 16; off; off >>= 1) {
        lx     += __shfl_down_sync(m, lx, off);
        ly     += __shfl_down_sync(m, ly, off);
        lw_    += __shfl_down_sync(m, lw_, off);
        lh_    += __shfl_down_sync(m, lh_, off);
        lobj   += __shfl_down_sync(m, lobj, off);
        lnoobj += __shfl_down_sync(m, lnoobj, off);
        lcls   += __shfl_down_sync(m, lcls, off);
    }
    if ((threadIdx.x & 31) == 0) {
        atomicAdd(&g_acc[0], (double)lx);
        atomicAdd(&g_acc[1], (double)ly);
        atomicAdd(&g_acc[2], (double)lw_);
        atomicAdd(&g_acc[3], (double)lh_);
        atomicAdd(&g_acc[4], (double)lobj);
        atomicAdd(&g_acc[5], (double)lnoobj);
        atomicAdd(&g_acc[6], (double)lcls);
    }
}

// ---------------- kernel 3: finalize ----------------
__global__ void fin_kernel(float* __restrict__ out) {
    double n = g_acc[7];
    float lx    = (float)(g_acc[0] / n);
    float ly    = (float)(g_acc[1] / n);
    float lw_   = (float)(g_acc[2] / n);
    float lh_   = (float)(g_acc[3] / n);
    float lconf = (float)(g_acc[4] / n + 0.5 * (g_acc[5] / n));
    float lcls  = (float)(g_acc[6] / n);
    out[0] = 2.5f * (lx + ly) + 2.5f * (lw_ + lh_) + 1.0f * lconf + 1.0f * lcls;
    out[1] = lx;
    out[2] = ly;
    out[3] = lw_;
    out[4] = lh_;
    out[5] = lconf;
    out[6] = lcls;
}

// ---------------- launch ----------------
extern "C" void kernel_launch(void* const* d_in, const int* in_sizes, int n_in,
                              void* d_out, int out_size) {
    const float* inp = (const float*)d_in[0];
    const float* tgt = (const float*)d_in[1];
    // safety: identify the (tiny) targets tensor by element count
    if (n_in >= 2 && in_sizes[0] == BS * TT * 5) {
        const float* tmp = inp; inp = tgt; tgt = tmp;
    }
    float* out = (float*)d_out;

    prep_kernel<<<1, 1024>>>(tgt);
    main_kernel<<<BS * BLKS_PER_B, TPB>>>(inp);
    fin_kernel<<<1, 1>>>(out);
}

// round 2
// speedup vs baseline: 4.0381x; 4.0381x over previous
#include <cuda_runtime.h>
#include <math.h>
#include <float.h>

// ---------------- problem constants ----------------
#define BS   16
#define TT   50
#define NA   3
#define NC   80
#define HH   76
#define WW   76
#define NCH  255
#define HW   (HH*WW)                              // 5776
#define CELLS_PER_B (NA*HW)                       // 17328
#define TPB  256
#define BLKS_PER_B ((CELLS_PER_B + TPB - 1)/TPB)  // 68
#define NBLK (BS*BLKS_PER_B)                      // 1088
#define FINF FLT_MAX

// ---------------- device scratch (static, no allocations) ----------------
__device__ float    g_tvals[BS*TT*5];             // tx, ty, tw, th, scale
__device__ int      g_owner[BS*CELLS_PER_B];      // 0 = none, else t+1 (last-writer-wins via atomicMax)
__device__ unsigned g_cls[BS*CELLS_PER_B*3];      // class bitmask per cell
__device__ float    g_sarea[BS*64];               // per-image target areas, sorted ascending, FLT_MAX padded
__device__ float4   g_sbox[BS*64];                // matching corners (x1,x2,y1,y2)
__device__ float    g_part[7*NBLK];               // per-block partial sums
__device__ float    g_nobj;

// scaled anchors (TOTAL / STRIDE=8)
__constant__ float c_staw[9] = {1.25f, 2.0f, 4.125f, 3.75f, 7.75f, 7.375f, 14.5f, 19.5f, 46.625f};
__constant__ float c_stah[9] = {1.625f, 3.75f, 2.875f, 7.625f, 5.625f, 14.875f, 11.25f, 24.75f, 40.75f};
__constant__ float c_saw[3]  = {1.25f, 2.0f, 4.125f};
__constant__ float c_sah[3]  = {1.625f, 3.75f, 2.875f};
__constant__ float c_apq[3]  = {2.03125f, 7.5f, 11.859375f};  // saw*sah

// ---------------- helpers ----------------
__device__ __forceinline__ float softplus(float z) {          // == -log(1-sigmoid(z)) == bce(sigmoid(z), 0)
    return __logf(1.0f + __expf(z));
}
__device__ __forceinline__ float sigm(float z) {
    return __fdividef(1.0f, 1.0f + __expf(-z));
}
__device__ __forceinline__ float safelog(float p) { return p > 0.f ? __logf(p) : -100.0f; }
__device__ __forceinline__ float bce(float p, float t) {
    return -(t * safelog(p) + (1.f - t) * safelog(1.f - p));
}
__device__ __forceinline__ float sl1(float p, float t) {
    float d = fabsf(p - t);
    return d < 1.f ? 0.5f * d * d : d - 0.5f;
}

// ---------------- kernel 1: target preprocess ----------------
__global__ void __launch_bounds__(1024) prep_kernel(const float* __restrict__ tgt) {
    __shared__ float s_area[BS][TT];
    int tid = threadIdx.x;
    int b = tid / TT, t = tid - b * TT;

    float gx = 0.f, gy = 0.f, gw = 0.f, gh = 0.f;
    float x1 = 0.f, x2 = 0.f, y1 = 0.f, y2 = 0.f, area = FINF;
    int valid = 0, wr = -1, gi = 0, gj = 0, clsi = 0;

    if (tid < BS * TT) {
        const float* p = tgt + (size_t)tid * 5;
        float t0 = p[0], t1 = p[1], t2 = p[2], t3 = p[3], t4 = p[4];
        valid = ((t0 + t1 + t2 + t3 + t4) != 0.f) ? 1 : 0;
        clsi = (int)t0;
        gx = t1 * (float)WW; gy = t2 * (float)HH;
        gw = t3 * (float)WW; gh = t4 * (float)HH;
        gi = (int)gx; gj = (int)gy;

        // anchor matching vs 9 total scaled anchors (exact corner-algebra simplification)
        float ga = gw * gh;
        float best = -1e30f; int bestn = 0;
#pragma unroll
        for (int n = 0; n < 9; n++) {
            float inter = fminf(gw, c_staw[n]) * fminf(gh, c_stah[n]);
            float v = inter / (ga + c_staw[n] * c_stah[n] - inter + 1e-16f);
            if (v > best) { best = v; bestn = n; }
        }
        wr = (valid && bestn < 3) ? bestn : -1;

        // corners + area exactly as reference computes them for the ignore IoU
        x1 = gx - gw * 0.5f; x2 = gx + gw * 0.5f;
        y1 = gy - gh * 0.5f; y2 = gy + gh * 0.5f;
        float carea = (x2 - x1) * (y2 - y1);
        area = valid ? carea : FINF;

        if (wr >= 0) {
            g_tvals[tid*5+0] = gx - (float)gi;
            g_tvals[tid*5+1] = gy - (float)gj;
            g_tvals[tid*5+2] = logf(gw / c_saw[wr] + 1e-16f);
            g_tvals[tid*5+3] = logf(gh / c_sah[wr] + 1e-16f);
            g_tvals[tid*5+4] = 2.0f - t3 * t4;
        }
        s_area[b][t] = area;
    }
    __syncthreads();

    // rank-sort (stable by index) into global sorted arrays; pad [50,64) with FLT_MAX
    if (tid < BS * TT) {
        int cnt = 0;
        for (int j2 = 0; j2 < TT; j2++) {
            float aj = s_area[b][j2];
            cnt += (aj < area) || (aj == area && j2 < t);
        }
        g_sarea[b*64 + cnt] = area;
        g_sbox [b*64 + cnt] = make_float4(x1, x2, y1, y2);
    } else {
        int k = tid - BS * TT;          // 0..223 == 16*14
        int bb = k / 14, kk = 50 + k % 14;
        g_sarea[bb*64 + kk] = FINF;
    }

    // owner scatter: clear -> barrier -> atomic write (last-writer == max t wins)
    int cell = -1;
    if (tid < BS * TT && wr >= 0) {
        cell = (b * NA + wr) * HW + gj * WW + gi;
        g_owner[cell] = 0;
        g_cls[cell*3+0] = 0; g_cls[cell*3+1] = 0; g_cls[cell*3+2] = 0;
    }
    int total = __syncthreads_count(tid < BS * TT && valid);
    if (cell >= 0) {
        atomicMax(&g_owner[cell], t + 1);
        atomicOr(&g_cls[cell*3 + (clsi >> 5)], 1u << (clsi & 31));
    }
    if (tid == 0) g_nobj = (float)total;
}

// ---------------- kernel 2: per-cell loss ----------------
__global__ void __launch_bounds__(TPB) main_kernel(const float* __restrict__ inp) {
    __shared__ float  s_area[64];
    __shared__ float4 s_box[64];
    __shared__ float  s_acc[7];

    int tid = threadIdx.x;
    int b = blockIdx.x / BLKS_PER_B;
    int local = (blockIdx.x % BLKS_PER_B) * TPB + tid;

    if (tid < 64) { s_area[tid] = g_sarea[b*64 + tid]; s_box[tid] = g_sbox[b*64 + tid]; }
    if (tid < 7)  s_acc[tid] = 0.f;
    __syncthreads();

    float v0 = 0.f, v1 = 0.f, v2 = 0.f, v3 = 0.f, v4 = 0.f, v5 = 0.f, v6 = 0.f;
    bool rare = false;

    if (local < CELLS_PER_B) {
        int a = local / HW;
        int r = local - a * HW;
        int j = r / WW;
        int i = r - j * WW;

        const float* base = inp + (size_t)(b * NCH + a * 85) * HW + r;
        float wv = base[2*HW];
        float hv = base[3*HW];
        float zc = base[4*HW];
        int owner = g_owner[b * CELLS_PER_B + local];

        if (owner) {
            // ------ rare path: this cell owns a target ------
            rare = true;
            int g = b * TT + owner - 1;
            float tx = g_tvals[g*5+0], ty = g_tvals[g*5+1];
            float tw = g_tvals[g*5+2], th = g_tvals[g*5+3];
            float sc = g_tvals[g*5+4];
            float sx = sigm(base[0]);
            float sy = sigm(base[HW]);
            v0 = sc * bce(sx, tx);
            v1 = sc * bce(sy, ty);
            v2 = sc * sl1(wv, tw);
            v3 = sc * sl1(hv, th);
            v4 = softplus(-zc);                 // bce(conf, 1)
            unsigned m0 = g_cls[(b*CELLS_PER_B + local)*3 + 0];
            unsigned m1 = g_cls[(b*CELLS_PER_B + local)*3 + 1];
            unsigned m2 = g_cls[(b*CELLS_PER_B + local)*3 + 2];
            float s = 0.f;
            for (int c = 0; c < NC; c++) {
                float z = base[(5 + c) * HW];
                unsigned bit = ((c < 32) ? (m0 >> c)
                              : (c < 64) ? (m1 >> (c - 32))
                                         : (m2 >> (c - 64))) & 1u;
                s += softplus(bit ? -z : z);    // bit: -log(pc) ; else: -log(1-pc)
            }
            v6 = s;
        } else {
            // ------ common path: ignore test via sorted-area prefilter ------
            float pa  = __expf(wv + hv) * c_apq[a];
            float paL = pa * 0.499f;            // IoU>=0.5 requires target area in [pa/2, 2pa]
            float paU = pa * 2.004f;            // (margin >> fp rounding, can't wrongly exclude)
            int lo = 0;
#pragma unroll
            for (int st = 32; st; st >>= 1)
                if (s_area[lo + st - 1] < paL) lo += st;
            bool ign = false;
            if (s_area[lo] >= paL && s_area[lo] <= paU) {
                float sx = sigm(base[0]);
                float sy = sigm(base[HW]);
                float pw = __expf(wv) * c_saw[a];
                float ph = __expf(hv) * c_sah[a];
                float px = sx + (float)i, py = sy + (float)j;
                float px1 = px - pw * 0.5f, px2 = px + pw * 0.5f;
                float py1 = py - ph * 0.5f, py2 = py + ph * 0.5f;
                float pa2 = (px2 - px1) * (py2 - py1);
                for (int idx = lo; idx < 64; idx++) {
                    float ta = s_area[idx];
                    if (ta > paU) break;
                    float4 tb = s_box[idx];
                    float iw = fmaxf(fminf(px2, tb.y) - fmaxf(px1, tb.x), 0.f);
                    float ih = fmaxf(fminf(py2, tb.w) - fmaxf(py1, tb.z), 0.f);
                    float inter = iw * ih;
                    float iou = __fdividef(inter, ta + pa2 - inter + 1e-16f);
                    if (iou >= 0.5f) { ign = true; break; }
                }
            }
            if (!ign) v5 = softplus(zc);        // bce(conf, 0), noobj cell
        }
    }

    // ------ reduction: lnoobj always; rare terms only if some lane has them ------
    unsigned full = 0xffffffffu;
    unsigned anyrare = __ballot_sync(full, rare);
#pragma unroll
    for (int o = 16; o; o >>= 1) v5 += __shfl_down_sync(full, v5, o);
    if (anyrare) {
#pragma unroll
        for (int o = 16; o; o >>= 1) {
            v0 += __shfl_down_sync(full, v0, o);
            v1 += __shfl_down_sync(full, v1, o);
            v2 += __shfl_down_sync(full, v2, o);
            v3 += __shfl_down_sync(full, v3, o);
            v4 += __shfl_down_sync(full, v4, o);
            v6 += __shfl_down_sync(full, v6, o);
        }
    }
    if ((tid & 31) == 0) {
        atomicAdd(&s_acc[5], v5);
        if (anyrare) {
            atomicAdd(&s_acc[0], v0);
            atomicAdd(&s_acc[1], v1);
            atomicAdd(&s_acc[2], v2);
            atomicAdd(&s_acc[3], v3);
            atomicAdd(&s_acc[4], v4);
            atomicAdd(&s_acc[6], v6);
        }
    }
    __syncthreads();
    if (tid < 7) g_part[tid * NBLK + blockIdx.x] = s_acc[tid];
}

// ---------------- kernel 3: finalize ----------------
__global__ void __launch_bounds__(256) fin_kernel(float* __restrict__ out) {
    __shared__ double s_sum[7];
    int tid = threadIdx.x;
    int w = tid >> 5, lane = tid & 31;
    if (w < 7) {
        double s = 0.0;
        for (int k = lane; k < NBLK; k += 32) s += (double)g_part[w * NBLK + k];
#pragma unroll
        for (int o = 16; o; o >>= 1) s += __shfl_down_sync(0xffffffffu, s, o);
        if (lane == 0) s_sum[w] = s;
    }
    __syncthreads();
    if (tid == 0) {
        double n = (double)g_nobj;
        double lx = s_sum[0] / n, ly = s_sum[1] / n;
        double lw = s_sum[2] / n, lh = s_sum[3] / n;
        double lconf = s_sum[4] / n + 0.5 * (s_sum[5] / n);
        double lcls  = s_sum[6] / n;
        out[0] = (float)(2.5 * (lx + ly) + 2.5 * (lw + lh) + lconf + lcls);
        out[1] = (float)lx;
        out[2] = (float)ly;
        out[3] = (float)lw;
        out[4] = (float)lh;
        out[5] = (float)lconf;
        out[6] = (float)lcls;
    }
}

// ---------------- launch ----------------
extern "C" void kernel_launch(void* const* d_in, const int* in_sizes, int n_in,
                              void* d_out, int out_size) {
    const float* inp = (const float*)d_in[0];
    const float* tgt = (const float*)d_in[1];
    if (n_in >= 2 && in_sizes[0] == BS * TT * 5) {   // identify tensors by size
        const float* tmp = inp; inp = tgt; tgt = tmp;
    }
    float* out = (float*)d_out;

    prep_kernel<<<1, 1024>>>(tgt);
    main_kernel<<<NBLK, TPB>>>(inp);
    fin_kernel<<<1, 256>>>(out);
}

// round 4
// speedup vs baseline: 4.3813x; 1.0850x over previous
#include <cuda_runtime.h>
#include <math.h>
#include <float.h>

// ---------------- problem constants ----------------
#define BS   16
#define TT   50
#define NA   3
#define NC   80
#define HH   76
#define WW   76
#define NCH  255
#define HW   (HH*WW)                              // 5776
#define CELLS_PER_B (NA*HW)                       // 17328
#define TPB  256
#define BLKS_PER_B ((CELLS_PER_B + TPB - 1)/TPB)  // 68
#define NBLK (BS*BLKS_PER_B)                      // 1088
#define FINF FLT_MAX

// ---------------- device scratch (static, no allocations) ----------------
__device__ float    g_part[7*NBLK];               // per-block partial sums
__device__ float    g_nobj_part[BS];              // per-image valid-target counts
__device__ unsigned g_count;                      // completion ticket (self-resetting)

// scaled anchors (TOTAL / STRIDE=8)
__constant__ float c_staw[9] = {1.25f, 2.0f, 4.125f, 3.75f, 7.75f, 7.375f, 14.5f, 19.5f, 46.625f};
__constant__ float c_stah[9] = {1.625f, 3.75f, 2.875f, 7.625f, 5.625f, 14.875f, 11.25f, 24.75f, 40.75f};
__constant__ float c_saw[3]  = {1.25f, 2.0f, 4.125f};
__constant__ float c_sah[3]  = {1.625f, 3.75f, 2.875f};
__constant__ float c_apq[3]  = {2.03125f, 7.5f, 11.859375f};  // saw*sah

// ---------------- helpers ----------------
__device__ __forceinline__ float softplus(float z) {          // == bce(sigmoid(z), 0)
    return __logf(1.0f + __expf(z));
}
__device__ __forceinline__ float sigm(float z) {
    return __fdividef(1.0f, 1.0f + __expf(-z));
}
__device__ __forceinline__ float safelog(float p) { return p > 0.f ? __logf(p) : -100.0f; }
__device__ __forceinline__ float bce(float p, float t) {
    return -(t * safelog(p) + (1.f - t) * safelog(1.f - p));
}
__device__ __forceinline__ float sl1(float p, float t) {
    float d = fabsf(p - t);
    return d < 1.f ? 0.5f * d * d : d - 0.5f;
}

// ---------------- the single fused kernel ----------------
__global__ void __launch_bounds__(TPB) yolo_kernel(const float* __restrict__ inp,
                                                   const float* __restrict__ tgt,
                                                   float* __restrict__ out) {
    __shared__ float    s_areaT[TT];        // unsorted areas (rank-sort input)
    __shared__ float    s_area[64];         // sorted ascending, FINF-padded
    __shared__ float4   s_box[64];          // sorted corners (x1,x2,y1,y2)
    __shared__ float    s_tvals[TT][5];     // tx, ty, tw, th, scale
    __shared__ int      s_owner[TPB];       // per-cell owner: 0 or t+1
    __shared__ unsigned s_clsb[TPB][3];     // per-cell class bitmask
    __shared__ float    s_acc[7];
    __shared__ unsigned s_ticket;
    __shared__ double   s_sum[7];

    int tid = threadIdx.x;
    int b   = blockIdx.x / BLKS_PER_B;
    int c0  = (blockIdx.x % BLKS_PER_B) * TPB;   // first cell (within image) of this block

    // ---- phase 0: clear shared ----
    s_owner[tid] = 0;
    s_clsb[tid][0] = 0; s_clsb[tid][1] = 0; s_clsb[tid][2] = 0;
    if (tid < 7) s_acc[tid] = 0.f;
    if (tid >= TT && tid < 64) s_area[tid] = FINF;

    // ---- phase 1: per-target prep (threads 0..49) ----
    float area = FINF, x1 = 0.f, x2 = 0.f, y1 = 0.f, y2 = 0.f;
    int valid = 0, cell = -1, clsi = 0;
    if (tid < TT) {
        const float* p = tgt + (size_t)(b * TT + tid) * 5;
        float t0 = p[0], t1 = p[1], t2 = p[2], t3 = p[3], t4 = p[4];
        valid = ((t0 + t1 + t2 + t3 + t4) != 0.f) ? 1 : 0;
        clsi  = (int)t0;
        float gx = t1 * (float)WW, gy = t2 * (float)HH;
        float gw = t3 * (float)WW, gh = t4 * (float)HH;
        int gi = (int)gx, gj = (int)gy;

        // anchor match vs 9 total scaled anchors; first-max argmax
        float ga = gw * gh;
        float best = -1e30f; int bestn = 0;
#pragma unroll
        for (int n = 0; n < 9; n++) {
            float inter = fminf(gw, c_staw[n]) * fminf(gh, c_stah[n]);
            float v = inter / (ga + c_staw[n] * c_stah[n] - inter + 1e-16f);
            if (v > best) { best = v; bestn = n; }
        }
        int wr = (valid && bestn < 3) ? bestn : -1;

        x1 = gx - gw * 0.5f; x2 = gx + gw * 0.5f;
        y1 = gy - gh * 0.5f; y2 = gy + gh * 0.5f;
        area = valid ? (x2 - x1) * (y2 - y1) : FINF;
        s_areaT[tid] = area;

        if (wr >= 0) {
            s_tvals[tid][0] = gx - (float)gi;
            s_tvals[tid][1] = gy - (float)gj;
            s_tvals[tid][2] = logf(gw / c_saw[wr] + 1e-16f);
            s_tvals[tid][3] = logf(gh / c_sah[wr] + 1e-16f);
            s_tvals[tid][4] = 2.0f - t3 * t4;
            cell = wr * HW + gj * WW + gi;
        }
    }
    // per-image valid count (identical across this image's blocks)
    int nobj_img = __syncthreads_count(tid < TT && valid);  // also syncs phase 0/1
    // first block of each image publishes its image's count
    if ((blockIdx.x % BLKS_PER_B) == 0 && tid == 0) g_nobj_part[b] = (float)nobj_img;

    // ---- phase 2: rank-sort + owner scatter into shared ----
    if (tid < TT) {
        int rank = 0;
        for (int j = 0; j < TT; j++) {
            float aj = s_areaT[j];
            rank += (aj < area) || (aj == area && j < tid);
        }
        s_area[rank] = area;
        s_box[rank]  = make_float4(x1, x2, y1, y2);
        if (cell >= c0 && cell < c0 + TPB) {             // last-writer-wins + class bit OR
            atomicMax(&s_owner[cell - c0], tid + 1);
            atomicOr(&s_clsb[cell - c0][clsi >> 5], 1u << (clsi & 31));
        }
    }
    __syncthreads();

    // ---- phase 3: per-cell loss ----
    float v0 = 0.f, v1 = 0.f, v2 = 0.f, v3 = 0.f, v4 = 0.f, v5 = 0.f, v6 = 0.f;
    bool rare = false;
    int local = c0 + tid;

    if (local < CELLS_PER_B) {
        int a = local / HW;
        int r = local - a * HW;
        int j = r / WW;
        int i = r - j * WW;

        const float* base = inp + (size_t)(b * NCH + a * 85) * HW + r;
        float wv = base[2*HW];
        float hv = base[3*HW];
        float zc = base[4*HW];
        int owner = s_owner[tid];

        if (owner) {
            // ------ rare: this cell owns a target ------
            rare = true;
            int g = owner - 1;
            float sx = sigm(base[0]);
            float sy = sigm(base[HW]);
            float sc = s_tvals[g][4];
            v0 = sc * bce(sx, s_tvals[g][0]);
            v1 = sc * bce(sy, s_tvals[g][1]);
            v2 = sc * sl1(wv, s_tvals[g][2]);
            v3 = sc * sl1(hv, s_tvals[g][3]);
            v4 = softplus(-zc);                           // bce(conf, 1)
            unsigned m0 = s_clsb[tid][0], m1 = s_clsb[tid][1], m2 = s_clsb[tid][2];
            float s = 0.f;
            for (int c = 0; c < NC; c++) {
                float z = base[(5 + c) * HW];
                unsigned bit = ((c < 32) ? (m0 >> c)
                              : (c < 64) ? (m1 >> (c - 32))
                                         : (m2 >> (c - 64))) & 1u;
                s += softplus(bit ? -z : z);
            }
            v6 = s;
        } else {
            // ------ common: ignore test via sorted-area prefilter ------
            float pa  = __expf(wv + hv) * c_apq[a];
            float paL = pa * 0.499f;     // IoU>=0.5 requires target area in [pa/2, 2pa]
            float paU = pa * 2.004f;     // margin >> fp rounding: never wrongly excludes
            int lo = 0;
#pragma unroll
            for (int st = 32; st; st >>= 1)
                if (s_area[lo + st - 1] < paL) lo += st;
            bool ign = false;
            if (s_area[lo] >= paL && s_area[lo] <= paU) {
                float sx = sigm(base[0]);
                float sy = sigm(base[HW]);
                float pw = __expf(wv) * c_saw[a];
                float ph = __expf(hv) * c_sah[a];
                float px = sx + (float)i, py = sy + (float)j;
                float px1 = px - pw * 0.5f, px2 = px + pw * 0.5f;
                float py1 = py - ph * 0.5f, py2 = py + ph * 0.5f;
                float pa2 = (px2 - px1) * (py2 - py1);
                for (int idx = lo; idx < 64; idx++) {
                    float ta = s_area[idx];
                    if (ta > paU) break;
                    float4 tb = s_box[idx];
                    float iw = fmaxf(fminf(px2, tb.y) - fmaxf(px1, tb.x), 0.f);
                    float ih = fmaxf(fminf(py2, tb.w) - fmaxf(py1, tb.z), 0.f);
                    float inter = iw * ih;
                    float iou = __fdividef(inter, ta + pa2 - inter + 1e-16f);
                    if (iou >= 0.5f) { ign = true; break; }
                }
            }
            if (!ign) v5 = softplus(zc);                  // bce(conf, 0)
        }
    }

    // ---- phase 4: block reduction ----
    unsigned full = 0xffffffffu;
    unsigned anyrare = __ballot_sync(full, rare);
#pragma unroll
    for (int o = 16; o; o >>= 1) v5 += __shfl_down_sync(full, v5, o);
    if (anyrare) {
#pragma unroll
        for (int o = 16; o; o >>= 1) {
            v0 += __shfl_down_sync(full, v0, o);
            v1 += __shfl_down_sync(full, v1, o);
            v2 += __shfl_down_sync(full, v2, o);
            v3 += __shfl_down_sync(full, v3, o);
            v4 += __shfl_down_sync(full, v4, o);
            v6 += __shfl_down_sync(full, v6, o);
        }
    }
    if ((tid & 31) == 0) {
        atomicAdd(&s_acc[5], v5);
        if (anyrare) {
            atomicAdd(&s_acc[0], v0);
            atomicAdd(&s_acc[1], v1);
            atomicAdd(&s_acc[2], v2);
            atomicAdd(&s_acc[3], v3);
            atomicAdd(&s_acc[4], v4);
            atomicAdd(&s_acc[6], v6);
        }
    }
    __syncthreads();
    if (tid < 7) g_part[tid * NBLK + blockIdx.x] = s_acc[tid];

    // ---- phase 5: last block finalizes ----
    __threadfence();
    if (tid == 0) s_ticket = atomicAdd(&g_count, 1u);
    __syncthreads();
    if (s_ticket == NBLK - 1) {
        __threadfence();
        int w = tid >> 5, lane = tid & 31;
        if (w < 7) {
            double s = 0.0;
            for (int k = lane; k < NBLK; k += 32) s += (double)g_part[w * NBLK + k];
#pragma unroll
            for (int o = 16; o; o >>= 1) s += __shfl_down_sync(full, s, o);
            if (lane == 0) s_sum[w] = s;
        } else if (w == 7) {
            // total valid targets across all images
            float nv = (lane < BS) ? g_nobj_part[lane] : 0.f;
#pragma unroll
            for (int o = 16; o; o >>= 1) nv += __shfl_down_sync(full, nv, o);
            if (lane == 0) s_sum[0 + 0] = s_sum[0]; // no-op placeholder avoided below
            if (lane == 0) ((volatile double*)s_sum)[7 - 7] = s_sum[0]; // (unused)
            if (lane == 0) s_ticket = __float_as_uint(nv);   // stash total in shared
        }
        __syncthreads();
        if (tid == 0) {
            g_count = 0;                                   // reset for next graph replay
            double n = (double)__uint_as_float(s_ticket);
            double lx = s_sum[0] / n, ly = s_sum[1] / n;
            double lw = s_sum[2] / n, lh = s_sum[3] / n;
            double lconf = s_sum[4] / n + 0.5 * (s_sum[5] / n);
            double lcls  = s_sum[6] / n;
            out[0] = (float)(2.5 * (lx + ly) + 2.5 * (lw + lh) + lconf + lcls);
            out[1] = (float)lx;
            out[2] = (float)ly;
            out[3] = (float)lw;
            out[4] = (float)lh;
            out[5] = (float)lconf;
            out[6] = (float)lcls;
        }
    }
}

// ---------------- launch ----------------
extern "C" void kernel_launch(void* const* d_in, const int* in_sizes, int n_in,
                              void* d_out, int out_size) {
    const float* inp = (const float*)d_in[0];
    const float* tgt = (const float*)d_in[1];
    if (n_in >= 2 && in_sizes[0] == BS * TT * 5) {   // identify tensors by size
        const float* tmp = inp; inp = tgt; tgt = tmp;
    }
    float* out = (float*)d_out;

    yolo_kernel<<<NBLK, TPB>>>(inp, tgt, out);
}